// round 16
// baseline (speedup 1.0000x reference)
#include <cuda_runtime.h>
#include <cuda_fp16.h>
#include <cstdint>

#define NN 8192
#define EE 1024
#define FF 256
#define NW (NN/32)   // 256 words per edge row (transposed bits)
#define EW (EE/32)   // 32 words per node row

// ---- scratch (no allocations allowed; device globals) ----
__device__ float    g_dvis[NN];                        // dv^{-1/2}
__device__ __align__(16) unsigned g_HbT[EE * NW];      // H^T bitpacked: [edge][node-word]
__device__ __align__(16) unsigned g_HbR[NN * EW];      // H bitpacked:   [node][edge-word]
__device__ __align__(16) __half g_Xsh[NN * FF];        // fp16(dvis*X)   row = 512B
__device__ __align__(16) float  g_M [EE * FF];         // edge features (fp32)
__device__ __align__(16) __half g_MWh[EE * FF];        // fp16(M @ W^T)  row = 512B

// half2 4-wide add of two uint4s (8 halves each)
__device__ __forceinline__ uint4 hadd8(uint4 a, uint4 b) {
    const __half2* ha = (const __half2*)&a;
    const __half2* hb = (const __half2*)&b;
    __half2 r0 = __hadd2(ha[0], hb[0]);
    __half2 r1 = __hadd2(ha[1], hb[1]);
    __half2 r2 = __hadd2(ha[2], hb[2]);
    __half2 r3 = __hadd2(ha[3], hb[3]);
    uint4 r;
    r.x = *(unsigned*)&r0; r.y = *(unsigned*)&r1;
    r.z = *(unsigned*)&r2; r.w = *(unsigned*)&r3;
    return r;
}

// accumulate 8 halves (one uint4) into 8 fp32 accumulators
__device__ __forceinline__ void acc_half8(float* a, uint4 v) {
    const __half2* h = (const __half2*)&v;
    float2 f0 = __half22float2(h[0]);
    float2 f1 = __half22float2(h[1]);
    float2 f2 = __half22float2(h[2]);
    float2 f3 = __half22float2(h[3]);
    a[0] += f0.x; a[1] += f0.y; a[2] += f1.x; a[3] += f1.y;
    a[4] += f2.x; a[5] += f2.y; a[6] += f3.x; a[7] += f3.y;
}

// ============================================================
// One-pass pack: coalesced read of H -> HbR, HbT (bit transpose),
// dv^{-1/2}, Xsh = fp16(dvis*X). CTA = 32 rows.
// ============================================================
__global__ void __launch_bounds__(256) pack_all(const float* __restrict__ H,
                                                const float* __restrict__ X) {
    const int r0 = blockIdx.x * 32;
    const int w  = threadIdx.x >> 5;
    const int l  = threadIdx.x & 31;
    const int tid = threadIdx.x;

    __shared__ unsigned smask[32][32];
    __shared__ float sdvr[32];

    int cnt[4] = {0, 0, 0, 0};
    for (int ch = 0; ch < 32; ch += 2) {
        float v[8];
        #pragma unroll
        for (int cc = 0; cc < 2; ++cc)
            #pragma unroll
            for (int k = 0; k < 4; ++k)
                v[cc * 4 + k] = H[(long)(r0 + w + 8 * k) * EE + (ch + cc) * 32 + l];
        #pragma unroll
        for (int cc = 0; cc < 2; ++cc)
            #pragma unroll
            for (int k = 0; k < 4; ++k) {
                unsigned m = __ballot_sync(0xffffffffu, v[cc * 4 + k] != 0.f);
                cnt[k] += __popc(m);
                if (l == 0) {
                    smask[ch + cc][w + 8 * k] = m;
                    g_HbR[(r0 + w + 8 * k) * EW + (ch + cc)] = m;
                }
            }
    }
    if (l == 0) {
        #pragma unroll
        for (int k = 0; k < 4; ++k) {
            float dv = rsqrtf((float)cnt[k]);
            g_dvis[r0 + w + 8 * k] = dv;
            sdvr[w + 8 * k] = dv;
        }
    }
    __syncthreads();

    // bit transpose -> HbT
    const int wordIdx = blockIdx.x;
    #pragma unroll
    for (int q = 0; q < 4; ++q) {
        const int cc = w + 8 * q;
        const unsigned rm = smask[cc][l];
        #pragma unroll
        for (int c = 0; c < 32; ++c) {
            unsigned colm = __ballot_sync(0xffffffffu, (rm >> c) & 1u);
            if (l == 0) g_HbT[(cc * 32 + c) * NW + wordIdx] = colm;
        }
    }

    // Xsh = fp16(dvis * X)
    const float4* X4 = (const float4*)X;
    uint4* Xs4 = (uint4*)g_Xsh;
    #pragma unroll
    for (int u = 0; u < 4; ++u) {
        int idx = tid + 256 * u;        // 0..1023
        int row = idx >> 5;
        int col = idx & 31;
        float dv = sdvr[row];
        float4 x0 = X4[(long)(r0 + row) * 64 + col * 2];
        float4 x1 = X4[(long)(r0 + row) * 64 + col * 2 + 1];
        __half2 h0 = __floats2half2_rn(x0.x * dv, x0.y * dv);
        __half2 h1 = __floats2half2_rn(x0.z * dv, x0.w * dv);
        __half2 h2 = __floats2half2_rn(x1.x * dv, x1.y * dv);
        __half2 h3 = __floats2half2_rn(x1.z * dv, x1.w * dv);
        uint4 o;
        o.x = *(unsigned*)&h0; o.y = *(unsigned*)&h1;
        o.z = *(unsigned*)&h2; o.w = *(unsigned*)&h3;
        Xs4[(long)(r0 + row) * 32 + col] = o;
    }
}

// ============================================================
// Pass A (r14-proven): M[e] = (1/de) * sum_{i in e} Xsh[i]
// 1 CTA per edge, 128 threads, 8-deep batches, 1-level HADD2 tree.
// ============================================================
__global__ void __launch_bounds__(128) edge_gather() {
    const int e = blockIdx.x;
    const int t = threadIdx.x;
    const int lane = t & 31, wid = t >> 5;

    __shared__ __align__(16) unsigned short sidx[1024];
    __shared__ int wtot[4];
    __shared__ int warpOff[5];
    __shared__ float red[128][8];

    uint2 mw = *(const uint2*)&g_HbT[e * NW + 2 * t];
    int cnt = __popc(mw.x) + __popc(mw.y);
    int scan = cnt;
    #pragma unroll
    for (int o = 1; o < 32; o <<= 1) {
        int v = __shfl_up_sync(0xffffffffu, scan, o);
        if (lane >= o) scan += v;
    }
    if (lane == 31) wtot[wid] = scan;
    __syncthreads();
    if (t == 0) {
        int s = 0;
        #pragma unroll
        for (int w = 0; w < 4; ++w) { warpOff[w] = s; s += wtot[w]; }
        warpOff[4] = s;
    }
    __syncthreads();

    int off = warpOff[wid] + (scan - cnt);
    {
        unsigned m = mw.x;
        int base = t * 64;
        while (m) {
            int b = __ffs(m) - 1; m &= m - 1;
            sidx[off++] = (unsigned short)(base + b);
        }
        m = mw.y;
        base += 32;
        while (m) {
            int b = __ffs(m) - 1; m &= m - 1;
            sidx[off++] = (unsigned short)(base + b);
        }
    }
    __syncthreads();

    const int total = warpOff[4];
    const int Q  = ((total + 31) >> 5) << 3;
    const int jb = wid * Q;
    const int je = min(jb + Q, total);

    const uint4* Xr = (const uint4*)g_Xsh;
    float a[8] = {0.f, 0.f, 0.f, 0.f, 0.f, 0.f, 0.f, 0.f};

    int j = jb;
    for (; j + 8 <= je; j += 8) {
        uint4 iw = *(const uint4*)&sidx[j];
        int n0 = iw.x & 0xffff, n1 = iw.x >> 16;
        int n2 = iw.y & 0xffff, n3 = iw.y >> 16;
        int n4 = iw.z & 0xffff, n5 = iw.z >> 16;
        int n6 = iw.w & 0xffff, n7 = iw.w >> 16;
        uint4 v0 = Xr[n0 * 32 + lane];
        uint4 v1 = Xr[n1 * 32 + lane];
        uint4 v2 = Xr[n2 * 32 + lane];
        uint4 v3 = Xr[n3 * 32 + lane];
        uint4 v4 = Xr[n4 * 32 + lane];
        uint4 v5 = Xr[n5 * 32 + lane];
        uint4 v6 = Xr[n6 * 32 + lane];
        uint4 v7 = Xr[n7 * 32 + lane];
        uint4 w0 = hadd8(v0, v1);
        uint4 w1 = hadd8(v2, v3);
        uint4 w2 = hadd8(v4, v5);
        uint4 w3 = hadd8(v6, v7);
        acc_half8(a, w0); acc_half8(a, w1);
        acc_half8(a, w2); acc_half8(a, w3);
    }
    for (; j < je; ++j)
        acc_half8(a, Xr[sidx[j] * 32 + lane]);

    #pragma unroll
    for (int k = 0; k < 8; ++k) red[t][k] = a[k];
    __syncthreads();

    if (wid == 0) {
        float di = 1.f / (float)total;
        float o[8];
        #pragma unroll
        for (int k = 0; k < 8; ++k)
            o[k] = (red[lane][k] + red[lane + 32][k] +
                    red[lane + 64][k] + red[lane + 96][k]) * di;
        float4 o0 = {o[0], o[1], o[2], o[3]};
        float4 o1 = {o[4], o[5], o[6], o[7]};
        *(float4*)&g_M[e * FF + lane * 8]     = o0;
        *(float4*)&g_M[e * FF + lane * 8 + 4] = o1;
    }
}

// ============================================================
// g_MWh = fp16(g_M @ W^T) — BM=16 x BN=32, 512 CTAs, 128 threads,
// reg->smem double buffer, 1 sync/chunk.
// ============================================================
__global__ void __launch_bounds__(128) gemm_mw(const float* __restrict__ Wm) {
    __shared__ float As[2][16][36];
    __shared__ float Bs[2][32][36];

    const int tid = threadIdx.x;
    const int row = tid >> 3;        // 0..15: edge row (compute + A load)
    const int tx  = tid & 7;         // 0..7: 4 feat cols each
    const int i0 = blockIdx.y * 16;
    const int o0 = blockIdx.x * 32;
    const int lk = (tid & 7) << 2;   // k offset for loads

    float acc[4] = {0.f, 0.f, 0.f, 0.f};

    float4 pa, pb[2];
    pa = *(const float4*)&g_M[(i0 + row) * FF + lk];
    #pragma unroll
    for (int l = 0; l < 2; ++l)
        pb[l] = *(const float4*)&Wm[(o0 + row + 16 * l) * FF + lk];
    *(float4*)&As[0][row][lk] = pa;
    #pragma unroll
    for (int l = 0; l < 2; ++l)
        *(float4*)&Bs[0][row + 16 * l][lk] = pb[l];
    __syncthreads();

    for (int c = 0; c < 8; ++c) {
        const int buf = c & 1;
        if (c < 7) {
            const int kc = (c + 1) * 32;
            pa = *(const float4*)&g_M[(i0 + row) * FF + kc + lk];
            #pragma unroll
            for (int l = 0; l < 2; ++l)
                pb[l] = *(const float4*)&Wm[(o0 + row + 16 * l) * FF + kc + lk];
        }
        #pragma unroll
        for (int k4 = 0; k4 < 8; ++k4) {
            float4 a4 = *(const float4*)&As[buf][row][k4 * 4];
            #pragma unroll
            for (int cc = 0; cc < 4; ++cc) {
                float4 b = *(const float4*)&Bs[buf][tx * 4 + cc][k4 * 4];
                acc[cc] = fmaf(a4.x, b.x, acc[cc]);
                acc[cc] = fmaf(a4.y, b.y, acc[cc]);
                acc[cc] = fmaf(a4.z, b.z, acc[cc]);
                acc[cc] = fmaf(a4.w, b.w, acc[cc]);
            }
        }
        if (c < 7) {
            const int nb = buf ^ 1;
            *(float4*)&As[nb][row][lk] = pa;
            #pragma unroll
            for (int l = 0; l < 2; ++l)
                *(float4*)&Bs[nb][row + 16 * l][lk] = pb[l];
            __syncthreads();
        }
    }

    __half2 h0 = __floats2half2_rn(acc[0], acc[1]);
    __half2 h1 = __floats2half2_rn(acc[2], acc[3]);
    uint2 o;
    o.x = *(unsigned*)&h0; o.y = *(unsigned*)&h1;
    *(uint2*)&g_MWh[(i0 + row) * FF + o0 + tx * 4] = o;
}

// ============================================================
// Pass B (r14-proven): out[i] = dvis[i] * sum_{e ni i} MWh[e] + b
// 4 independent warps/CTA, 8-deep batches, 2-level HADD2 tree.
// ============================================================
__global__ void __launch_bounds__(128) node_gather(const float* __restrict__ bias,
                                                   float* __restrict__ out) {
    const int wid  = threadIdx.x >> 5;
    const int lane = threadIdx.x & 31;
    const int i    = blockIdx.x * 4 + wid;

    __shared__ __align__(16) unsigned short sidx[4][128];

    unsigned m = g_HbR[i * EW + lane];
    int cnt = __popc(m);
    int scan = cnt;
    #pragma unroll
    for (int o = 1; o < 32; o <<= 1) {
        int v = __shfl_up_sync(0xffffffffu, scan, o);
        if (lane >= o) scan += v;
    }
    const int total = __shfl_sync(0xffffffffu, scan, 31);
    int off = scan - cnt;
    {
        const int base = lane * 32;
        while (m) {
            int b = __ffs(m) - 1; m &= m - 1;
            sidx[wid][off++] = (unsigned short)(base + b);
        }
    }
    __syncwarp();

    const unsigned short* idx = sidx[wid];
    const uint4* MWr = (const uint4*)g_MWh;
    float a[8] = {0.f, 0.f, 0.f, 0.f, 0.f, 0.f, 0.f, 0.f};

    int j = 0;
    for (; j + 8 <= total; j += 8) {
        uint4 iw = *(const uint4*)&idx[j];
        int e0 = iw.x & 0xffff, e1 = iw.x >> 16;
        int e2 = iw.y & 0xffff, e3 = iw.y >> 16;
        int e4 = iw.z & 0xffff, e5 = iw.z >> 16;
        int e6 = iw.w & 0xffff, e7 = iw.w >> 16;
        uint4 v0 = MWr[e0 * 32 + lane];
        uint4 v1 = MWr[e1 * 32 + lane];
        uint4 v2 = MWr[e2 * 32 + lane];
        uint4 v3 = MWr[e3 * 32 + lane];
        uint4 v4 = MWr[e4 * 32 + lane];
        uint4 v5 = MWr[e5 * 32 + lane];
        uint4 v6 = MWr[e6 * 32 + lane];
        uint4 v7 = MWr[e7 * 32 + lane];
        uint4 w0 = hadd8(v0, v1);
        uint4 w1 = hadd8(v2, v3);
        uint4 w2 = hadd8(v4, v5);
        uint4 w3 = hadd8(v6, v7);
        uint4 x0 = hadd8(w0, w1);
        uint4 x1 = hadd8(w2, w3);
        acc_half8(a, x0); acc_half8(a, x1);
    }
    for (; j < total; ++j)
        acc_half8(a, MWr[idx[j] * 32 + lane]);

    const float dv = g_dvis[i];
    const float4* b4 = (const float4*)bias;
    float4 bv0 = b4[lane * 2];
    float4 bv1 = b4[lane * 2 + 1];
    float4 o0, o1;
    o0.x = fmaf(a[0], dv, bv0.x); o0.y = fmaf(a[1], dv, bv0.y);
    o0.z = fmaf(a[2], dv, bv0.z); o0.w = fmaf(a[3], dv, bv0.w);
    o1.x = fmaf(a[4], dv, bv1.x); o1.y = fmaf(a[5], dv, bv1.y);
    o1.z = fmaf(a[6], dv, bv1.z); o1.w = fmaf(a[7], dv, bv1.w);
    *(float4*)&out[(long)i * FF + lane * 8]     = o0;
    *(float4*)&out[(long)i * FF + lane * 8 + 4] = o1;
}

// ============================================================
extern "C" void kernel_launch(void* const* d_in, const int* in_sizes, int n_in,
                              void* d_out, int out_size) {
    const float* X    = (const float*)d_in[0];   // [8192,256]
    const float* H    = (const float*)d_in[1];   // [8192,1024]
    const float* Wm   = (const float*)d_in[2];   // [256,256]
    const float* bias = (const float*)d_in[3];   // [256]
    float* out = (float*)d_out;

    pack_all   <<<NN / 32, 256>>>(H, X);
    edge_gather<<<EE, 128>>>();
    dim3 g1(FF / 32, EE / 16);     // 8 x 64 = 512 CTAs
    gemm_mw    <<<g1, 128>>>(Wm);
    node_gather<<<NN / 4, 128>>>(bias, out);
}

// round 17
// speedup vs baseline: 1.3004x; 1.3004x over previous
#include <cuda_runtime.h>
#include <cuda_fp16.h>
#include <cstdint>

#define NN 8192
#define EE 1024
#define FF 256
#define NW (NN/32)   // 256 words per edge row (transposed bits)
#define EW (EE/32)   // 32 words per node row

// ---- scratch (no allocations allowed; device globals) ----
__device__ float    g_dvis[NN];                        // dv^{-1/2}
__device__ __align__(16) unsigned g_HbT[EE * NW];      // H^T bitpacked: [edge][node-word]
__device__ __align__(16) unsigned g_HbR[NN * EW];      // H bitpacked:   [node][edge-word]
__device__ __align__(16) __half g_Xsh[NN * FF];        // fp16(dvis*X)   row = 512B
__device__ __align__(16) float  g_M [EE * FF];         // edge features (fp32)
__device__ __align__(16) __half g_MWh[EE * FF];        // fp16(M @ W^T)  row = 512B

// half2 4-wide add of two uint4s (8 halves each)
__device__ __forceinline__ uint4 hadd8(uint4 a, uint4 b) {
    const __half2* ha = (const __half2*)&a;
    const __half2* hb = (const __half2*)&b;
    __half2 r0 = __hadd2(ha[0], hb[0]);
    __half2 r1 = __hadd2(ha[1], hb[1]);
    __half2 r2 = __hadd2(ha[2], hb[2]);
    __half2 r3 = __hadd2(ha[3], hb[3]);
    uint4 r;
    r.x = *(unsigned*)&r0; r.y = *(unsigned*)&r1;
    r.z = *(unsigned*)&r2; r.w = *(unsigned*)&r3;
    return r;
}

// accumulate 8 halves (one uint4) into 8 fp32 accumulators
__device__ __forceinline__ void acc_half8(float* a, uint4 v) {
    const __half2* h = (const __half2*)&v;
    float2 f0 = __half22float2(h[0]);
    float2 f1 = __half22float2(h[1]);
    float2 f2 = __half22float2(h[2]);
    float2 f3 = __half22float2(h[3]);
    a[0] += f0.x; a[1] += f0.y; a[2] += f1.x; a[3] += f1.y;
    a[4] += f2.x; a[5] += f2.y; a[6] += f3.x; a[7] += f3.y;
}

// ============================================================
// One-pass pack: coalesced read of H -> HbR, HbT (bit transpose),
// dv^{-1/2}, Xsh = fp16(dvis*X). CTA = 32 rows.
// ============================================================
__global__ void __launch_bounds__(256) pack_all(const float* __restrict__ H,
                                                const float* __restrict__ X) {
    const int r0 = blockIdx.x * 32;
    const int w  = threadIdx.x >> 5;
    const int l  = threadIdx.x & 31;
    const int tid = threadIdx.x;

    __shared__ unsigned smask[32][32];
    __shared__ float sdvr[32];

    int cnt[4] = {0, 0, 0, 0};
    for (int ch = 0; ch < 32; ch += 2) {
        float v[8];
        #pragma unroll
        for (int cc = 0; cc < 2; ++cc)
            #pragma unroll
            for (int k = 0; k < 4; ++k)
                v[cc * 4 + k] = H[(long)(r0 + w + 8 * k) * EE + (ch + cc) * 32 + l];
        #pragma unroll
        for (int cc = 0; cc < 2; ++cc)
            #pragma unroll
            for (int k = 0; k < 4; ++k) {
                unsigned m = __ballot_sync(0xffffffffu, v[cc * 4 + k] != 0.f);
                cnt[k] += __popc(m);
                if (l == 0) {
                    smask[ch + cc][w + 8 * k] = m;
                    g_HbR[(r0 + w + 8 * k) * EW + (ch + cc)] = m;
                }
            }
    }
    if (l == 0) {
        #pragma unroll
        for (int k = 0; k < 4; ++k) {
            float dv = rsqrtf((float)cnt[k]);
            g_dvis[r0 + w + 8 * k] = dv;
            sdvr[w + 8 * k] = dv;
        }
    }
    __syncthreads();

    // bit transpose -> HbT
    const int wordIdx = blockIdx.x;
    #pragma unroll
    for (int q = 0; q < 4; ++q) {
        const int cc = w + 8 * q;
        const unsigned rm = smask[cc][l];
        #pragma unroll
        for (int c = 0; c < 32; ++c) {
            unsigned colm = __ballot_sync(0xffffffffu, (rm >> c) & 1u);
            if (l == 0) g_HbT[(cc * 32 + c) * NW + wordIdx] = colm;
        }
    }

    // Xsh = fp16(dvis * X)
    const float4* X4 = (const float4*)X;
    uint4* Xs4 = (uint4*)g_Xsh;
    #pragma unroll
    for (int u = 0; u < 4; ++u) {
        int idx = tid + 256 * u;        // 0..1023
        int row = idx >> 5;
        int col = idx & 31;
        float dv = sdvr[row];
        float4 x0 = X4[(long)(r0 + row) * 64 + col * 2];
        float4 x1 = X4[(long)(r0 + row) * 64 + col * 2 + 1];
        __half2 h0 = __floats2half2_rn(x0.x * dv, x0.y * dv);
        __half2 h1 = __floats2half2_rn(x0.z * dv, x0.w * dv);
        __half2 h2 = __floats2half2_rn(x1.x * dv, x1.y * dv);
        __half2 h3 = __floats2half2_rn(x1.z * dv, x1.w * dv);
        uint4 o;
        o.x = *(unsigned*)&h0; o.y = *(unsigned*)&h1;
        o.z = *(unsigned*)&h2; o.w = *(unsigned*)&h3;
        Xs4[(long)(r0 + row) * 32 + col] = o;
    }
}

// ============================================================
// Pass A: M[e] = (1/de) * sum_{i in e} Xsh[i]
// 1 CTA per edge, 128 threads, 8-deep batches, 2-level HADD2 tree.
// ============================================================
__global__ void __launch_bounds__(128) edge_gather() {
    const int e = blockIdx.x;
    const int t = threadIdx.x;
    const int lane = t & 31, wid = t >> 5;

    __shared__ __align__(16) unsigned short sidx[1024];
    __shared__ int wtot[4];
    __shared__ int warpOff[5];
    __shared__ float red[128][8];

    uint2 mw = *(const uint2*)&g_HbT[e * NW + 2 * t];
    int cnt = __popc(mw.x) + __popc(mw.y);
    int scan = cnt;
    #pragma unroll
    for (int o = 1; o < 32; o <<= 1) {
        int v = __shfl_up_sync(0xffffffffu, scan, o);
        if (lane >= o) scan += v;
    }
    if (lane == 31) wtot[wid] = scan;
    __syncthreads();
    if (t == 0) {
        int s = 0;
        #pragma unroll
        for (int w = 0; w < 4; ++w) { warpOff[w] = s; s += wtot[w]; }
        warpOff[4] = s;
    }
    __syncthreads();

    int off = warpOff[wid] + (scan - cnt);
    {
        unsigned m = mw.x;
        int base = t * 64;
        while (m) {
            int b = __ffs(m) - 1; m &= m - 1;
            sidx[off++] = (unsigned short)(base + b);
        }
        m = mw.y;
        base += 32;
        while (m) {
            int b = __ffs(m) - 1; m &= m - 1;
            sidx[off++] = (unsigned short)(base + b);
        }
    }
    __syncthreads();

    const int total = warpOff[4];
    const int Q  = ((total + 31) >> 5) << 3;
    const int jb = wid * Q;
    const int je = min(jb + Q, total);

    const uint4* Xr = (const uint4*)g_Xsh;
    float a[8] = {0.f, 0.f, 0.f, 0.f, 0.f, 0.f, 0.f, 0.f};

    int j = jb;
    for (; j + 8 <= je; j += 8) {
        uint4 iw = *(const uint4*)&sidx[j];
        int n0 = iw.x & 0xffff, n1 = iw.x >> 16;
        int n2 = iw.y & 0xffff, n3 = iw.y >> 16;
        int n4 = iw.z & 0xffff, n5 = iw.z >> 16;
        int n6 = iw.w & 0xffff, n7 = iw.w >> 16;
        uint4 v0 = Xr[n0 * 32 + lane];
        uint4 v1 = Xr[n1 * 32 + lane];
        uint4 v2 = Xr[n2 * 32 + lane];
        uint4 v3 = Xr[n3 * 32 + lane];
        uint4 v4 = Xr[n4 * 32 + lane];
        uint4 v5 = Xr[n5 * 32 + lane];
        uint4 v6 = Xr[n6 * 32 + lane];
        uint4 v7 = Xr[n7 * 32 + lane];
        // 2-level fp16 pair tree, then fp32 accumulate
        uint4 w0 = hadd8(v0, v1);
        uint4 w1 = hadd8(v2, v3);
        uint4 w2 = hadd8(v4, v5);
        uint4 w3 = hadd8(v6, v7);
        uint4 x0 = hadd8(w0, w1);
        uint4 x1 = hadd8(w2, w3);
        acc_half8(a, x0); acc_half8(a, x1);
    }
    for (; j < je; ++j)
        acc_half8(a, Xr[sidx[j] * 32 + lane]);

    #pragma unroll
    for (int k = 0; k < 8; ++k) red[t][k] = a[k];
    __syncthreads();

    if (wid == 0) {
        float di = 1.f / (float)total;
        float o[8];
        #pragma unroll
        for (int k = 0; k < 8; ++k)
            o[k] = (red[lane][k] + red[lane + 32][k] +
                    red[lane + 64][k] + red[lane + 96][k]) * di;
        float4 o0 = {o[0], o[1], o[2], o[3]};
        float4 o1 = {o[4], o[5], o[6], o[7]};
        *(float4*)&g_M[e * FF + lane * 8]     = o0;
        *(float4*)&g_M[e * FF + lane * 8 + 4] = o1;
    }
}

// ============================================================
// g_MWh = fp16(g_M @ W^T) — BM=32 x BN=32, 256 CTAs, 128 threads,
// reg->smem double buffer, 1 sync/chunk. (r14-proven version)
// ============================================================
__global__ void __launch_bounds__(128) gemm_mw(const float* __restrict__ Wm) {
    __shared__ float As[2][32][36];
    __shared__ float Bs[2][32][36];

    const int tid = threadIdx.x;
    const int ty = tid >> 3;
    const int tx = tid & 7;
    const int i0 = blockIdx.y * 32;
    const int o0 = blockIdx.x * 32;

    const int li = tid >> 3;
    const int lk = (tid & 7) << 2;

    float acc[2][4];
    #pragma unroll
    for (int r = 0; r < 2; ++r)
        #pragma unroll
        for (int c = 0; c < 4; ++c) acc[r][c] = 0.f;

    float4 pa[2], pb[2];
    #pragma unroll
    for (int l = 0; l < 2; ++l) {
        pa[l] = *(const float4*)&g_M[(i0 + li + 16 * l) * FF + lk];
        pb[l] = *(const float4*)&Wm [(o0 + li + 16 * l) * FF + lk];
    }
    #pragma unroll
    for (int l = 0; l < 2; ++l) {
        *(float4*)&As[0][li + 16 * l][lk] = pa[l];
        *(float4*)&Bs[0][li + 16 * l][lk] = pb[l];
    }
    __syncthreads();

    for (int c = 0; c < 8; ++c) {
        const int buf = c & 1;
        if (c < 7) {
            const int kc = (c + 1) * 32;
            #pragma unroll
            for (int l = 0; l < 2; ++l) {
                pa[l] = *(const float4*)&g_M[(i0 + li + 16 * l) * FF + kc + lk];
                pb[l] = *(const float4*)&Wm [(o0 + li + 16 * l) * FF + kc + lk];
            }
        }
        #pragma unroll
        for (int k4 = 0; k4 < 8; ++k4) {
            float4 a0 = *(const float4*)&As[buf][ty * 2 + 0][k4 * 4];
            float4 a1 = *(const float4*)&As[buf][ty * 2 + 1][k4 * 4];
            #pragma unroll
            for (int cc = 0; cc < 4; ++cc) {
                float4 b = *(const float4*)&Bs[buf][tx * 4 + cc][k4 * 4];
                acc[0][cc] = fmaf(a0.x, b.x, acc[0][cc]);
                acc[0][cc] = fmaf(a0.y, b.y, acc[0][cc]);
                acc[0][cc] = fmaf(a0.z, b.z, acc[0][cc]);
                acc[0][cc] = fmaf(a0.w, b.w, acc[0][cc]);
                acc[1][cc] = fmaf(a1.x, b.x, acc[1][cc]);
                acc[1][cc] = fmaf(a1.y, b.y, acc[1][cc]);
                acc[1][cc] = fmaf(a1.z, b.z, acc[1][cc]);
                acc[1][cc] = fmaf(a1.w, b.w, acc[1][cc]);
            }
        }
        if (c < 7) {
            const int nb = buf ^ 1;
            #pragma unroll
            for (int l = 0; l < 2; ++l) {
                *(float4*)&As[nb][li + 16 * l][lk] = pa[l];
                *(float4*)&Bs[nb][li + 16 * l][lk] = pb[l];
            }
            __syncthreads();
        }
    }

    #pragma unroll
    for (int r = 0; r < 2; ++r) {
        int i = i0 + ty * 2 + r;
        __half2 h0 = __floats2half2_rn(acc[r][0], acc[r][1]);
        __half2 h1 = __floats2half2_rn(acc[r][2], acc[r][3]);
        uint2 o;
        o.x = *(unsigned*)&h0; o.y = *(unsigned*)&h1;
        *(uint2*)&g_MWh[i * FF + o0 + tx * 4] = o;
    }
}

// ============================================================
// Pass B: out[i] = dvis[i] * sum_{e ni i} MWh[e] + b
// 4 independent warps/CTA, 8-deep batches, 3-level HADD2 tree.
// ============================================================
__global__ void __launch_bounds__(128) node_gather(const float* __restrict__ bias,
                                                   float* __restrict__ out) {
    const int wid  = threadIdx.x >> 5;
    const int lane = threadIdx.x & 31;
    const int i    = blockIdx.x * 4 + wid;

    __shared__ __align__(16) unsigned short sidx[4][128];

    unsigned m = g_HbR[i * EW + lane];
    int cnt = __popc(m);
    int scan = cnt;
    #pragma unroll
    for (int o = 1; o < 32; o <<= 1) {
        int v = __shfl_up_sync(0xffffffffu, scan, o);
        if (lane >= o) scan += v;
    }
    const int total = __shfl_sync(0xffffffffu, scan, 31);
    int off = scan - cnt;
    {
        const int base = lane * 32;
        while (m) {
            int b = __ffs(m) - 1; m &= m - 1;
            sidx[wid][off++] = (unsigned short)(base + b);
        }
    }
    __syncwarp();

    const unsigned short* idx = sidx[wid];
    const uint4* MWr = (const uint4*)g_MWh;
    float a[8] = {0.f, 0.f, 0.f, 0.f, 0.f, 0.f, 0.f, 0.f};

    int j = 0;
    for (; j + 8 <= total; j += 8) {
        uint4 iw = *(const uint4*)&idx[j];
        int e0 = iw.x & 0xffff, e1 = iw.x >> 16;
        int e2 = iw.y & 0xffff, e3 = iw.y >> 16;
        int e4 = iw.z & 0xffff, e5 = iw.z >> 16;
        int e6 = iw.w & 0xffff, e7 = iw.w >> 16;
        uint4 v0 = MWr[e0 * 32 + lane];
        uint4 v1 = MWr[e1 * 32 + lane];
        uint4 v2 = MWr[e2 * 32 + lane];
        uint4 v3 = MWr[e3 * 32 + lane];
        uint4 v4 = MWr[e4 * 32 + lane];
        uint4 v5 = MWr[e5 * 32 + lane];
        uint4 v6 = MWr[e6 * 32 + lane];
        uint4 v7 = MWr[e7 * 32 + lane];
        // 3-level fp16 pair tree (values ~1e-2; far from fp16 range limits)
        uint4 w0 = hadd8(v0, v1);
        uint4 w1 = hadd8(v2, v3);
        uint4 w2 = hadd8(v4, v5);
        uint4 w3 = hadd8(v6, v7);
        uint4 x0 = hadd8(w0, w1);
        uint4 x1 = hadd8(w2, w3);
        uint4 y0 = hadd8(x0, x1);
        acc_half8(a, y0);
    }
    for (; j < total; ++j)
        acc_half8(a, MWr[idx[j] * 32 + lane]);

    const float dv = g_dvis[i];
    const float4* b4 = (const float4*)bias;
    float4 bv0 = b4[lane * 2];
    float4 bv1 = b4[lane * 2 + 1];
    float4 o0, o1;
    o0.x = fmaf(a[0], dv, bv0.x); o0.y = fmaf(a[1], dv, bv0.y);
    o0.z = fmaf(a[2], dv, bv0.z); o0.w = fmaf(a[3], dv, bv0.w);
    o1.x = fmaf(a[4], dv, bv1.x); o1.y = fmaf(a[5], dv, bv1.y);
    o1.z = fmaf(a[6], dv, bv1.z); o1.w = fmaf(a[7], dv, bv1.w);
    *(float4*)&out[(long)i * FF + lane * 8]     = o0;
    *(float4*)&out[(long)i * FF + lane * 8 + 4] = o1;
}

// ============================================================
extern "C" void kernel_launch(void* const* d_in, const int* in_sizes, int n_in,
                              void* d_out, int out_size) {
    const float* X    = (const float*)d_in[0];   // [8192,256]
    const float* H    = (const float*)d_in[1];   // [8192,1024]
    const float* Wm   = (const float*)d_in[2];   // [256,256]
    const float* bias = (const float*)d_in[3];   // [256]
    float* out = (float*)d_out;

    pack_all   <<<NN / 32, 256>>>(H, X);
    edge_gather<<<EE, 128>>>();
    dim3 g1(FF / 32, EE / 32);     // 256 CTAs
    gemm_mw    <<<g1, 128>>>(Wm);
    node_gather<<<NN / 4, 128>>>(bias, out);
}